// round 4
// baseline (speedup 1.0000x reference)
#include <cuda_runtime.h>
#include <cstdint>

#define BATCH 128
#define SEQ   512
#define IDIM  256
#define HDIM  512
#define G4    2048

// ---- persistent scan tiling ----
#define NBLK  128     // 4 batch-tiles x 32 j-tiles; all co-resident
#define NTHR  1024    // 32 warps -> 8 warps/SMSP; k-split by 2
#define BJ    16      // j per block
#define BB    32      // batches per block
#define KC    64      // k chunk staged in smem (per half)
#define KHALF 256     // k range per half-thread
#define WROW  516     // padded weight row (floats)
#define SROW  68      // padded staging row (floats): 272B, rows -> distinct banks
#define STG_FLOATS (4 * BB * SROW)             // sh[2] + sc[2]
#define SMEM_SCAN ((80*WROW + STG_FLOATS) * 4)

// ---- device-global scratch (no cudaMalloc allowed) ----
__device__ float g_h[2][BATCH][HDIM];
__device__ float g_c[2][BATCH][HDIM];
__device__ float g_u[SEQ][BATCH][G4];      // 512 MB precomputed input projection
__device__ unsigned g_bar[2];              // [0]=count, [1]=generation

// packed fp32x2 FMA (Blackwell-only; 2x FFMA throughput vs 3-reg FFMA)
__device__ __forceinline__ unsigned long long fma2(unsigned long long a,
                                                   unsigned long long b,
                                                   unsigned long long c) {
    unsigned long long d;
    asm("fma.rn.f32x2 %0, %1, %2, %3;" : "=l"(d) : "l"(a), "l"(b), "l"(c));
    return d;
}
__device__ __forceinline__ float red2(unsigned long long a) {
    return __uint_as_float((unsigned)a) + __uint_as_float((unsigned)(a >> 32));
}
__device__ __forceinline__ float sigm(float x) {
    return 1.0f / (1.0f + __expf(-x));
}

// =====================================================================
// Kernel 1: u_pre[s][b][g] = inputs[b][s][:] . U_all_w[g][:] + U_all_b[g]
// =====================================================================
__global__ void __launch_bounds__(256)
u_gemm_kernel(const float* __restrict__ X, const float* __restrict__ Uw,
              const float* __restrict__ Ub) {
    __shared__ float As[64][36];
    __shared__ float Bs[64][36];
    const int g0 = blockIdx.x * 64;
    const int r0 = blockIdx.y * 64;
    const int tid = threadIdx.x;
    const int tx = tid & 15, ty = tid >> 4;

    unsigned long long acc[4][4] = {};

    for (int k0 = 0; k0 < IDIM; k0 += 32) {
#pragma unroll
        for (int q = 0; q < 2; ++q) {
            int idx = tid + q * 256;
            int row = idx >> 3;
            int c4  = (idx & 7) << 2;
            *(float4*)&As[row][c4] = *(const float4*)&X[(size_t)(r0 + row) * IDIM + k0 + c4];
            *(float4*)&Bs[row][c4] = *(const float4*)&Uw[(size_t)(g0 + row) * IDIM + k0 + c4];
        }
        __syncthreads();
#pragma unroll
        for (int k = 0; k < 32; k += 2) {
            unsigned long long a[4], b[4];
#pragma unroll
            for (int i = 0; i < 4; ++i) a[i] = *(const unsigned long long*)&As[ty * 4 + i][k];
#pragma unroll
            for (int i = 0; i < 4; ++i) b[i] = *(const unsigned long long*)&Bs[tx * 4 + i][k];
#pragma unroll
            for (int mi = 0; mi < 4; ++mi)
#pragma unroll
                for (int ni = 0; ni < 4; ++ni)
                    acc[mi][ni] = fma2(a[mi], b[ni], acc[mi][ni]);
        }
        __syncthreads();
    }
#pragma unroll
    for (int mi = 0; mi < 4; ++mi) {
        int r = r0 + ty * 4 + mi;
        int b = r >> 9;          // batch
        int s = r & 511;         // step
        float* orow = &g_u[s][b][0];
#pragma unroll
        for (int ni = 0; ni < 4; ++ni) {
            int g = g0 + tx * 4 + ni;
            orow[g] = red2(acc[mi][ni]) + Ub[g];
        }
    }
}

// =====================================================================
// Kernel 2: persistent scan. 128 CTAs x 1024 threads (8 warps/SMSP).
// k-split: threads with kh=0 own k[0:256), kh=1 own k[256:512); partial
// sums combined via a small SMEM reduction before the epilogue.
// Weights resident in SMEM for all 512 steps; h/c ping-pong via L2.
// =====================================================================
__global__ void __launch_bounds__(NTHR, 1)
timelstm_scan_kernel(const float* __restrict__ Wall, const float* __restrict__ Wallb,
                     const float* __restrict__ Wd,   const float* __restrict__ Wdb,
                     const float* __restrict__ ts,   float* __restrict__ out) {
    extern __shared__ float sm[];
    float* sWg  = sm;                        // 64 rows (4 gates x 16 j) x WROW
    float* sWd  = sWg + 64 * WROW;           // 16 rows x WROW
    float* stg  = sWd + 16 * WROW;           // staging: sh[2][32][SROW], sc[2][32][SROW]
    float* sred = stg;                       // 5*512 floats, reuses staging (dead then)

    const int tid  = threadIdx.x;
    const int lane = tid & 31;
    const int warp = tid >> 5;
    const int kh   = tid >> 9;               // k-half: 0 or 1
    const int wl   = warp & 15;              // warp id within half
    const int jt = blockIdx.x >> 2;          // 0..31
    const int bt = blockIdx.x & 3;           // 0..3
    const int j0 = jt * BJ;
    const int b0 = bt * BB;

    const int bl = (wl & 3) * 8 + (lane & 7);     // local batch 0..31
    const int jj = (wl >> 2) * 4 + (lane >> 3);   // local j     0..15
    const int b  = b0 + bl;
    const int j  = j0 + jj;
    const int oid = bl * BJ + jj;                 // 0..511

    // ---- preload weights into SMEM (once for all 512 steps) ----
    for (int idx = tid; idx < 64 * (HDIM / 4); idx += NTHR) {
        int row = idx >> 7;                  // 128 float4 per row
        int c4  = (idx & 127) << 2;
        int g = row >> 4, jl = row & 15;
        *(float4*)&sWg[row * WROW + c4] =
            *(const float4*)&Wall[(size_t)(g * HDIM + j0 + jl) * HDIM + c4];
    }
    for (int idx = tid; idx < 16 * (HDIM / 4); idx += NTHR) {
        int row = idx >> 7;
        int c4  = (idx & 127) << 2;
        *(float4*)&sWd[row * WROW + c4] =
            *(const float4*)&Wd[(size_t)(j0 + row) * HDIM + c4];
    }
    const float bf  = Wallb[0 * HDIM + j];
    const float bi_ = Wallb[1 * HDIM + j];
    const float bo  = Wallb[2 * HDIM + j];
    const float bct = Wallb[3 * HDIM + j];
    const float bd  = Wdb[j];
    __syncthreads();

    // weight row bases for this thread's k-half (other gates via constant offsets)
    const float* wF = sWg + (0 * 16 + jj) * WROW + kh * KHALF;
    const float* wI = sWg + (1 * 16 + jj) * WROW + kh * KHALF;
    const float* wO = sWg + (2 * 16 + jj) * WROW + kh * KHALF;
    const float* wC = sWg + (3 * 16 + jj) * WROW + kh * KHALF;
    const float* wD = sWd + jj * WROW + kh * KHALF;

    float* sh_kh = stg + kh * (BB * SROW);
    float* sc_kh = stg + (2 + kh) * (BB * SROW);
    const float* hrow = sh_kh + bl * SROW;
    const float* crow = sc_kh + bl * SROW;

    const int ht   = tid & 511;              // staging index within half
    const int srow = ht >> 4;                // 0..31
    const int sc4  = (ht & 15) << 2;         // 0..60

    for (int s = 0; s < SEQ; ++s) {
        const int cur = s & 1, nxt = cur ^ 1;

        // epilogue operands prefetched early (only the kh=0 half needs them)
        float uf = 0, ui = 0, uo = 0, uct = 0, tv = 0, cold = 0;
        if (kh == 0) {
            const float* ub = &g_u[s][b][0];
            uf   = ub[j];
            ui   = ub[HDIM + j];
            uo   = ub[2 * HDIM + j];
            uct  = ub[3 * HDIM + j];
            tv   = ts[(size_t)b * SEQ + s];
            cold = __ldcg(&g_c[cur][b][j]);
        }

        unsigned long long aF = 0, aI = 0, aO = 0, aC = 0, aD = 0;

        for (int kci = 0; kci < KHALF / KC; ++kci) {   // 4 chunks of 64
            const int k0 = kh * KHALF + kci * KC;
            __syncthreads();   // previous chunk fully consumed (both halves)
            *(float4*)&sh_kh[srow * SROW + sc4] =
                __ldcg((const float4*)&g_h[cur][b0 + srow][k0 + sc4]);
            *(float4*)&sc_kh[srow * SROW + sc4] =
                __ldcg((const float4*)&g_c[cur][b0 + srow][k0 + sc4]);
            __syncthreads();

#pragma unroll 2
            for (int kk = 0; kk < KC; kk += 4) {
                const int kw = kci * KC + kk;        // within this half's 256
                ulonglong2 vF = *(const ulonglong2*)(wF + kw);
                ulonglong2 vI = *(const ulonglong2*)(wI + kw);
                ulonglong2 vO = *(const ulonglong2*)(wO + kw);
                ulonglong2 vC = *(const ulonglong2*)(wC + kw);
                ulonglong2 vD = *(const ulonglong2*)(wD + kw);
                ulonglong2 hv = *(const ulonglong2*)(hrow + kk);
                ulonglong2 cv = *(const ulonglong2*)(crow + kk);
                aF = fma2(hv.x, vF.x, aF);
                aI = fma2(hv.x, vI.x, aI);
                aO = fma2(hv.x, vO.x, aO);
                aC = fma2(hv.x, vC.x, aC);
                aD = fma2(cv.x, vD.x, aD);
                aF = fma2(hv.y, vF.y, aF);
                aI = fma2(hv.y, vI.y, aI);
                aO = fma2(hv.y, vO.y, aO);
                aC = fma2(hv.y, vC.y, aC);
                aD = fma2(cv.y, vD.y, aD);
            }
        }

        // ---- combine k-halves: kh=1 publishes partials, kh=0 finishes ----
        __syncthreads();
        if (kh == 1) {
            sred[0 * 512 + oid] = red2(aF);
            sred[1 * 512 + oid] = red2(aI);
            sred[2 * 512 + oid] = red2(aO);
            sred[3 * 512 + oid] = red2(aC);
            sred[4 * 512 + oid] = red2(aD);
        }
        __syncthreads();
        if (kh == 0) {
            float F  = red2(aF) + sred[0 * 512 + oid] + bf  + uf;
            float I_ = red2(aI) + sred[1 * 512 + oid] + bi_ + ui;
            float O_ = red2(aO) + sred[2 * 512 + oid] + bo  + uo;
            float Ct = red2(aC) + sred[3 * 512 + oid] + bct + uct;
            float D  = red2(aD) + sred[4 * 512 + oid] + bd;
            float f  = sigm(F);
            float ii = sigm(I_);
            float oo = sigm(O_);
            float ct = sigm(Ct);
            float cs1 = tanhf(D);
            float cadj = cold + cs1 * (tv - 1.0f);   // c - cs1 + cs1*t
            float cnew = f * cadj + ii * ct;
            float hnew = oo * tanhf(cnew);
            g_c[nxt][b][j] = cnew;
            g_h[nxt][b][j] = hnew;
            out[((size_t)b * SEQ + s) * HDIM + j] = hnew;
        }

        // ---- grid barrier (sense via generation counter) ----
        __syncthreads();
        if (tid == 0) {
            volatile unsigned* vgen = &g_bar[1];
            unsigned gen = *vgen;
            __threadfence();
            if (atomicAdd(&g_bar[0], 1u) == NBLK - 1u) {
                g_bar[0] = 0u;
                __threadfence();
                *vgen = gen + 1u;
            } else {
                while (*vgen == gen) { }
            }
            __threadfence();
        }
        __syncthreads();
    }
}

// =====================================================================
extern "C" void kernel_launch(void* const* d_in, const int* in_sizes, int n_in,
                              void* d_out, int out_size) {
    const float* X     = (const float*)d_in[0];   // inputs   [B,S,I]
    const float* T     = (const float*)d_in[1];   // timestamps [B,S]
    const float* Wall  = (const float*)d_in[2];   // W_all_w  [4H,H]
    const float* Wallb = (const float*)d_in[3];   // W_all_b  [4H]
    const float* Uw    = (const float*)d_in[4];   // U_all_w  [4H,I]
    const float* Ubb   = (const float*)d_in[5];   // U_all_b  [4H]
    const float* Wd    = (const float*)d_in[6];   // W_d_w    [H,H]
    const float* Wdb   = (const float*)d_in[7];   // W_d_b    [H]
    float* out = (float*)d_out;

    void *hp, *cp, *bp;
    cudaGetSymbolAddress(&hp, g_h);
    cudaGetSymbolAddress(&cp, g_c);
    cudaGetSymbolAddress(&bp, g_bar);
    cudaMemsetAsync(hp, 0, sizeof(float) * 2 * BATCH * HDIM, 0);
    cudaMemsetAsync(cp, 0, sizeof(float) * 2 * BATCH * HDIM, 0);
    cudaMemsetAsync(bp, 0, sizeof(unsigned) * 2, 0);

    dim3 ugrid(G4 / 64, (BATCH * SEQ) / 64);
    u_gemm_kernel<<<ugrid, 256>>>(X, Uw, Ubb);

    cudaFuncSetAttribute(timelstm_scan_kernel,
                         cudaFuncAttributeMaxDynamicSharedMemorySize, SMEM_SCAN);
    timelstm_scan_kernel<<<NBLK, NTHR, SMEM_SCAN>>>(Wall, Wallb, Wd, Wdb, T, out);
}

// round 5
// speedup vs baseline: 1.5881x; 1.5881x over previous
#include <cuda_runtime.h>
#include <cstdint>

#define BATCH 128
#define SEQ   512
#define IDIM  256
#define HDIM  512
#define G4    2048

// ---- persistent scan tiling ----
#define NBLK  128     // 4 batch-tiles x 32 j-tiles; all co-resident
#define NTHR  512     // 16 warps
#define BJ    16      // j per block
#define BB    32      // batches per block
#define WROW  528     // weight row: 4 quarters x (128 + 4 pad) floats
#define QOFF  132     // quarter offset inside weight row (4-bank shift)
#define GOFF  (16*WROW)  // gate offset in sWg
#define SROW  36      // staging row floats (32 + 4 pad)
#define QSTR  1156    // staging quarter stride = 32*36 + 4 (4-bank shift)
#define SMEM_SCAN ((80*WROW + 8*QSTR) * 4)

// ---- device-global scratch (no cudaMalloc allowed) ----
__device__ float g_h[2][BATCH][HDIM];
__device__ float g_c[2][BATCH][HDIM];
__device__ float g_u[SEQ][BATCH][G4];      // 512 MB precomputed input projection
__device__ unsigned g_bar[2];              // [0]=count, [1]=generation

__device__ __forceinline__ unsigned long long fma2(unsigned long long a,
                                                   unsigned long long b,
                                                   unsigned long long c) {
    unsigned long long d;
    asm("fma.rn.f32x2 %0, %1, %2, %3;" : "=l"(d) : "l"(a), "l"(b), "l"(c));
    return d;
}
__device__ __forceinline__ float red2(unsigned long long a) {
    return __uint_as_float((unsigned)a) + __uint_as_float((unsigned)(a >> 32));
}
__device__ __forceinline__ float sigm(float x) {
    return 1.0f / (1.0f + __expf(-x));
}

// =====================================================================
// Kernel 1: u_pre[s][b][g] = inputs[b][s][:] . U_all_w[g][:] + U_all_b[g]
// 64x64 tile, 128 threads, thread = 4m x 8n, k-packed f32x2.
// =====================================================================
__global__ void __launch_bounds__(128)
u_gemm_kernel(const float* __restrict__ X, const float* __restrict__ Uw,
              const float* __restrict__ Ub) {
    __shared__ float As[64][36];
    __shared__ float Bs[64][36];
    const int g0 = blockIdx.x * 64;
    const int r0 = blockIdx.y * 64;
    const int tid = threadIdx.x;
    const int tx = tid & 7;          // n base (n = tx + ni*8 -> bank-spread)
    const int ty = tid >> 3;         // m group (m = ty*4 + mi)

    unsigned long long acc[4][8] = {};

    for (int k0 = 0; k0 < IDIM; k0 += 32) {
#pragma unroll
        for (int q = 0; q < 4; ++q) {
            int idx = tid + q * 128;            // 0..511
            int row = idx >> 3;
            int c4  = (idx & 7) << 2;
            *(float4*)&As[row][c4] = *(const float4*)&X[(size_t)(r0 + row) * IDIM + k0 + c4];
            *(float4*)&Bs[row][c4] = *(const float4*)&Uw[(size_t)(g0 + row) * IDIM + k0 + c4];
        }
        __syncthreads();
#pragma unroll
        for (int k = 0; k < 32; k += 2) {
            unsigned long long a[4], b[8];
#pragma unroll
            for (int mi = 0; mi < 4; ++mi) a[mi] = *(const unsigned long long*)&As[ty * 4 + mi][k];
#pragma unroll
            for (int ni = 0; ni < 8; ++ni) b[ni] = *(const unsigned long long*)&Bs[tx + ni * 8][k];
#pragma unroll
            for (int mi = 0; mi < 4; ++mi)
#pragma unroll
                for (int ni = 0; ni < 8; ++ni)
                    acc[mi][ni] = fma2(a[mi], b[ni], acc[mi][ni]);
        }
        __syncthreads();
    }
#pragma unroll
    for (int mi = 0; mi < 4; ++mi) {
        int r = r0 + ty * 4 + mi;
        int b = r >> 9;          // batch
        int s = r & 511;         // step
        float* orow = &g_u[s][b][0];
#pragma unroll
        for (int ni = 0; ni < 8; ++ni) {
            int g = g0 + tx + ni * 8;
            orow[g] = red2(acc[mi][ni]) + Ub[g];
        }
    }
}

// =====================================================================
// Kernel 2: persistent scan. 128 CTAs x 512 threads (16 warps).
// Thread = 2 batches x 2 j x 1 k-quarter (128 k). 20 fma2 accumulators.
// lane = bg*2 + kqh ; warp = jp*2 + kqt  ->  kq = kqt*2 + kqh.
// k-quarter partials combined via shfl.bfly(1) + small SMEM exchange.
// Weights SMEM-resident (quarter-padded rows -> conflict-free LDS).
// =====================================================================
__global__ void __launch_bounds__(NTHR, 1)
timelstm_scan_kernel(const float* __restrict__ Wall, const float* __restrict__ Wallb,
                     const float* __restrict__ Wd,   const float* __restrict__ Wdb,
                     const float* __restrict__ ts,   float* __restrict__ out) {
    extern __shared__ float sm[];
    float* sWg  = sm;                        // 64 rows (4 gates x 16 j) x WROW
    float* sWd  = sWg + 64 * WROW;           // 16 rows x WROW
    float* stgh = sWd + 16 * WROW;           // 4 quarters x 32 x SROW (+pad)
    float* stgc = stgh + 4 * QSTR;
    float* sred = stgh;                      // 5*512 floats, reuses staging

    const int tid  = threadIdx.x;
    const int lane = tid & 31;
    const int warp = tid >> 5;
    const int bg   = lane >> 1;              // 0..15
    const int kqh  = lane & 1;
    const int jp   = warp >> 1;              // 0..7
    const int kqt  = warp & 1;
    const int kq   = kqt * 2 + kqh;          // k-quarter 0..3

    const int jt = blockIdx.x >> 2;
    const int bt = blockIdx.x & 3;
    const int j0 = jt * BJ;
    const int b0 = bt * BB;

    const int jlA = jp;                      // j-locals handled by this thread
    const int jlB = jp + 8;
    const int bl0 = bg * 2;                  // local batches
    const int bl1 = bl0 + 1;

    // ---- preload weights into SMEM with quarter-padded rows ----
    for (int idx = tid; idx < 64 * 128; idx += NTHR) {
        int row = idx >> 7;
        int kf  = (idx & 127) << 2;          // global k of float4
        int qtr = kf >> 7, kin = kf & 127;
        int g = row >> 4, jl = row & 15;
        *(float4*)&sWg[row * WROW + qtr * QOFF + kin] =
            *(const float4*)&Wall[(size_t)(g * HDIM + j0 + jl) * HDIM + kf];
    }
    for (int idx = tid; idx < 16 * 128; idx += NTHR) {
        int row = idx >> 7;
        int kf  = (idx & 127) << 2;
        int qtr = kf >> 7, kin = kf & 127;
        *(float4*)&sWd[row * WROW + qtr * QOFF + kin] =
            *(const float4*)&Wd[(size_t)(j0 + row) * HDIM + kf];
    }
    // epilogue j for this thread (kqt==0 lanes do the final math)
    const int jle = jp + kqh * 8;
    const int je  = j0 + jle;
    const float bF  = Wallb[0 * HDIM + je];
    const float bI  = Wallb[1 * HDIM + je];
    const float bO  = Wallb[2 * HDIM + je];
    const float bCt = Wallb[3 * HDIM + je];
    const float bD  = Wdb[je];
    __syncthreads();

    const float* wA  = sWg + jlA * WROW + kq * QOFF;   // gate g at +g*GOFF
    const float* wB  = sWg + jlB * WROW + kq * QOFF;
    const float* wDA = sWd + jlA * WROW + kq * QOFF;
    const float* wDB = sWd + jlB * WROW + kq * QOFF;
    const float* hrow0 = stgh + kq * QSTR + bl0 * SROW;
    const float* hrow1 = hrow0 + SROW;
    const float* crow0 = stgc + kq * QSTR + bl0 * SROW;
    const float* crow1 = crow0 + SROW;

    for (int s = 0; s < SEQ; ++s) {
        const int cur = s & 1, nxt = cur ^ 1;

        // epilogue operand prefetch (kqt==0 lanes only)
        float uf[2], ui[2], uo[2], uct[2], tv[2], cold[2];
        if (kqt == 0) {
#pragma unroll
            for (int q = 0; q < 2; ++q) {
                int be = b0 + bl0 + q;
                const float* ub = &g_u[s][be][0];
                uf[q]  = ub[je];
                ui[q]  = ub[HDIM + je];
                uo[q]  = ub[2 * HDIM + je];
                uct[q] = ub[3 * HDIM + je];
                tv[q]  = ts[(size_t)be * SEQ + s];
                cold[q] = __ldcg(&g_c[cur][be][je]);
            }
        }

        unsigned long long aF[2][2] = {}, aI[2][2] = {}, aO[2][2] = {},
                           aC[2][2] = {}, aD[2][2] = {};

#pragma unroll 1
        for (int kci = 0; kci < 4; ++kci) {
            __syncthreads();   // previous chunk consumed / sred free
#pragma unroll
            for (int q = 0; q < 2; ++q) {
                int idx = tid + q * NTHR;        // 0..1023
                int qtr = idx >> 8;
                int row = (idx >> 3) & 31;
                int c4  = (idx & 7) << 2;
                int gk  = qtr * 128 + kci * 32 + c4;
                *(float4*)&stgh[qtr * QSTR + row * SROW + c4] =
                    __ldcg((const float4*)&g_h[cur][b0 + row][gk]);
                *(float4*)&stgc[qtr * QSTR + row * SROW + c4] =
                    __ldcg((const float4*)&g_c[cur][b0 + row][gk]);
            }
            __syncthreads();

            const float* wAk  = wA  + kci * 32;
            const float* wBk  = wB  + kci * 32;
            const float* wDAk = wDA + kci * 32;
            const float* wDBk = wDB + kci * 32;
#pragma unroll
            for (int kk = 0; kk < 32; kk += 4) {
                ulonglong2 hv0 = *(const ulonglong2*)(hrow0 + kk);
                ulonglong2 hv1 = *(const ulonglong2*)(hrow1 + kk);
                ulonglong2 cv0 = *(const ulonglong2*)(crow0 + kk);
                ulonglong2 cv1 = *(const ulonglong2*)(crow1 + kk);
                // ---- j = jlA ----
                {
                    ulonglong2 vF = *(const ulonglong2*)(wAk + 0 * GOFF + kk);
                    ulonglong2 vI = *(const ulonglong2*)(wAk + 1 * GOFF + kk);
                    ulonglong2 vO = *(const ulonglong2*)(wAk + 2 * GOFF + kk);
                    ulonglong2 vC = *(const ulonglong2*)(wAk + 3 * GOFF + kk);
                    ulonglong2 vD = *(const ulonglong2*)(wDAk + kk);
                    aF[0][0] = fma2(hv0.x, vF.x, aF[0][0]); aF[0][0] = fma2(hv0.y, vF.y, aF[0][0]);
                    aF[0][1] = fma2(hv1.x, vF.x, aF[0][1]); aF[0][1] = fma2(hv1.y, vF.y, aF[0][1]);
                    aI[0][0] = fma2(hv0.x, vI.x, aI[0][0]); aI[0][0] = fma2(hv0.y, vI.y, aI[0][0]);
                    aI[0][1] = fma2(hv1.x, vI.x, aI[0][1]); aI[0][1] = fma2(hv1.y, vI.y, aI[0][1]);
                    aO[0][0] = fma2(hv0.x, vO.x, aO[0][0]); aO[0][0] = fma2(hv0.y, vO.y, aO[0][0]);
                    aO[0][1] = fma2(hv1.x, vO.x, aO[0][1]); aO[0][1] = fma2(hv1.y, vO.y, aO[0][1]);
                    aC[0][0] = fma2(hv0.x, vC.x, aC[0][0]); aC[0][0] = fma2(hv0.y, vC.y, aC[0][0]);
                    aC[0][1] = fma2(hv1.x, vC.x, aC[0][1]); aC[0][1] = fma2(hv1.y, vC.y, aC[0][1]);
                    aD[0][0] = fma2(cv0.x, vD.x, aD[0][0]); aD[0][0] = fma2(cv0.y, vD.y, aD[0][0]);
                    aD[0][1] = fma2(cv1.x, vD.x, aD[0][1]); aD[0][1] = fma2(cv1.y, vD.y, aD[0][1]);
                }
                // ---- j = jlB ----
                {
                    ulonglong2 vF = *(const ulonglong2*)(wBk + 0 * GOFF + kk);
                    ulonglong2 vI = *(const ulonglong2*)(wBk + 1 * GOFF + kk);
                    ulonglong2 vO = *(const ulonglong2*)(wBk + 2 * GOFF + kk);
                    ulonglong2 vC = *(const ulonglong2*)(wBk + 3 * GOFF + kk);
                    ulonglong2 vD = *(const ulonglong2*)(wDBk + kk);
                    aF[1][0] = fma2(hv0.x, vF.x, aF[1][0]); aF[1][0] = fma2(hv0.y, vF.y, aF[1][0]);
                    aF[1][1] = fma2(hv1.x, vF.x, aF[1][1]); aF[1][1] = fma2(hv1.y, vF.y, aF[1][1]);
                    aI[1][0] = fma2(hv0.x, vI.x, aI[1][0]); aI[1][0] = fma2(hv0.y, vI.y, aI[1][0]);
                    aI[1][1] = fma2(hv1.x, vI.x, aI[1][1]); aI[1][1] = fma2(hv1.y, vI.y, aI[1][1]);
                    aO[1][0] = fma2(hv0.x, vO.x, aO[1][0]); aO[1][0] = fma2(hv0.y, vO.y, aO[1][0]);
                    aO[1][1] = fma2(hv1.x, vO.x, aO[1][1]); aO[1][1] = fma2(hv1.y, vO.y, aO[1][1]);
                    aC[1][0] = fma2(hv0.x, vC.x, aC[1][0]); aC[1][0] = fma2(hv0.y, vC.y, aC[1][0]);
                    aC[1][1] = fma2(hv1.x, vC.x, aC[1][1]); aC[1][1] = fma2(hv1.y, vC.y, aC[1][1]);
                    aD[1][0] = fma2(cv0.x, vD.x, aD[1][0]); aD[1][0] = fma2(cv0.y, vD.y, aD[1][0]);
                    aD[1][1] = fma2(cv1.x, vD.x, aD[1][1]); aD[1][1] = fma2(cv1.y, vD.y, aD[1][1]);
                }
            }
        }

        // ---- combine k-quarters ----
        float p[2][2][5];
#pragma unroll
        for (int js = 0; js < 2; ++js)
#pragma unroll
            for (int bs = 0; bs < 2; ++bs) {
                p[js][bs][0] = red2(aF[js][bs]);
                p[js][bs][1] = red2(aI[js][bs]);
                p[js][bs][2] = red2(aO[js][bs]);
                p[js][bs][3] = red2(aC[js][bs]);
                p[js][bs][4] = red2(aD[js][bs]);
            }
#pragma unroll
        for (int js = 0; js < 2; ++js)
#pragma unroll
            for (int bs = 0; bs < 2; ++bs)
#pragma unroll
                for (int g = 0; g < 5; ++g)
                    p[js][bs][g] += __shfl_xor_sync(0xffffffffu, p[js][bs][g], 1);

        __syncthreads();            // all LDS reads of staging done
        if (kqt == 1) {             // publish own-j half (js == kqh)
            const int js = kqh;
            const int jl = jp + js * 8;
#pragma unroll
            for (int bs = 0; bs < 2; ++bs) {
                int bl = bl0 + bs;
#pragma unroll
                for (int g = 0; g < 5; ++g)
                    sred[g * 512 + bl * 16 + jl] = p[js][bs][g];
            }
        }
        __syncthreads();
        if (kqt == 0) {
            const int js = kqh;
#pragma unroll
            for (int bs = 0; bs < 2; ++bs) {
                int bl = bl0 + bs;
                int be = b0 + bl;
                float F  = p[js][bs][0] + sred[0 * 512 + bl * 16 + jle] + bF  + uf[bs];
                float I_ = p[js][bs][1] + sred[1 * 512 + bl * 16 + jle] + bI  + ui[bs];
                float O_ = p[js][bs][2] + sred[2 * 512 + bl * 16 + jle] + bO  + uo[bs];
                float Ct = p[js][bs][3] + sred[3 * 512 + bl * 16 + jle] + bCt + uct[bs];
                float D  = p[js][bs][4] + sred[4 * 512 + bl * 16 + jle] + bD;
                float f   = sigm(F);
                float ii  = sigm(I_);
                float oo  = sigm(O_);
                float ct  = sigm(Ct);
                float cs1 = tanhf(D);
                float cadj = cold[bs] + cs1 * (tv[bs] - 1.0f);   // c - cs1 + cs1*t
                float cnew = f * cadj + ii * ct;
                float hnew = oo * tanhf(cnew);
                g_c[nxt][be][je] = cnew;
                g_h[nxt][be][je] = hnew;
                out[((size_t)be * SEQ + s) * HDIM + je] = hnew;
            }
        }

        // ---- grid barrier ----
        __syncthreads();
        if (tid == 0) {
            volatile unsigned* vgen = &g_bar[1];
            unsigned gen = *vgen;
            __threadfence();
            if (atomicAdd(&g_bar[0], 1u) == NBLK - 1u) {
                g_bar[0] = 0u;
                __threadfence();
                *vgen = gen + 1u;
            } else {
                while (*vgen == gen) { }
            }
            __threadfence();
        }
        __syncthreads();
    }
}

// =====================================================================
extern "C" void kernel_launch(void* const* d_in, const int* in_sizes, int n_in,
                              void* d_out, int out_size) {
    const float* X     = (const float*)d_in[0];   // inputs   [B,S,I]
    const float* T     = (const float*)d_in[1];   // timestamps [B,S]
    const float* Wall  = (const float*)d_in[2];   // W_all_w  [4H,H]
    const float* Wallb = (const float*)d_in[3];   // W_all_b  [4H]
    const float* Uw    = (const float*)d_in[4];   // U_all_w  [4H,I]
    const float* Ubb   = (const float*)d_in[5];   // U_all_b  [4H]
    const float* Wd    = (const float*)d_in[6];   // W_d_w    [H,H]
    const float* Wdb   = (const float*)d_in[7];   // W_d_b    [H]
    float* out = (float*)d_out;

    void *hp, *cp, *bp;
    cudaGetSymbolAddress(&hp, g_h);
    cudaGetSymbolAddress(&cp, g_c);
    cudaGetSymbolAddress(&bp, g_bar);
    cudaMemsetAsync(hp, 0, sizeof(float) * 2 * BATCH * HDIM, 0);
    cudaMemsetAsync(cp, 0, sizeof(float) * 2 * BATCH * HDIM, 0);
    cudaMemsetAsync(bp, 0, sizeof(unsigned) * 2, 0);

    dim3 ugrid(G4 / 64, (BATCH * SEQ) / 64);
    u_gemm_kernel<<<ugrid, 128>>>(X, Uw, Ubb);

    cudaFuncSetAttribute(timelstm_scan_kernel,
                         cudaFuncAttributeMaxDynamicSharedMemorySize, SMEM_SCAN);
    timelstm_scan_kernel<<<NBLK, NTHR, SMEM_SCAN>>>(Wall, Wallb, Wd, Wdb, T, out);
}